// round 5
// baseline (speedup 1.0000x reference)
#include <cuda_runtime.h>

#define TPTS 64          // points per tile
#define H    256
#define EDIM 63
#define PSTR 68          // padded point-stride in shared (floats); 272B = 17*16B

typedef unsigned long long u64;
struct __align__(16) u64x2 { u64 x, y; };

// ---- packed f32x2 helpers (FFMA2 is PTX-only on sm_103a) ----
__device__ __forceinline__ u64 pk2(float w) {
    u64 r; asm("mov.b64 %0, {%1, %1};" : "=l"(r) : "f"(w)); return r;
}
__device__ __forceinline__ void fma2(u64 &a, u64 x, u64 w) {
    asm("fma.rn.f32x2 %0, %1, %2, %0;" : "+l"(a) : "l"(x), "l"(w));
}
__device__ __forceinline__ u64 add2(u64 a, u64 b) {
    u64 r; asm("add.rn.f32x2 %0, %1, %2;" : "=l"(r) : "l"(a), "l"(b)); return r;
}
__device__ __forceinline__ u64 mul2(u64 a, u64 b) {
    u64 r; asm("mul.rn.f32x2 %0, %1, %2;" : "=l"(r) : "l"(a), "l"(b)); return r;
}
__device__ __forceinline__ u64 relu2(u64 a) {
    float lo, hi;
    asm("mov.b64 {%0, %1}, %2;" : "=f"(lo), "=f"(hi) : "l"(a));
    lo = fmaxf(lo, 0.0f); hi = fmaxf(hi, 0.0f);
    u64 r; asm("mov.b64 %0, {%1, %2};" : "=l"(r) : "f"(lo), "f"(hi)); return r;
}
__device__ __forceinline__ u64 shfl_xor_u64(u64 v, int off) {
    unsigned lo = (unsigned)v, hi = (unsigned)(v >> 32);
    lo = __shfl_xor_sync(0xffffffffu, lo, off);
    hi = __shfl_xor_sync(0xffffffffu, hi, off);
    return ((u64)hi << 32) | lo;
}

// One input row i: acc[jj*8+kk] += in[i][m0+2kk..+1] * W[i][j0+jj]
// (4 neurons x 16 points per thread)
__device__ __forceinline__ void accum_row(u64 acc[32], const float* __restrict__ W,
                                          const float* in_s, int i, int j0, int m0)
{
    float4 wv = *(const float4*)(W + i * H + j0);          // LDG.128: 4 neuron weights
    u64 w0 = pk2(wv.x), w1 = pk2(wv.y), w2 = pk2(wv.z), w3 = pk2(wv.w);
    const u64x2* row = (const u64x2*)(in_s + i * PSTR + m0);
    u64x2 v0 = row[0], v1 = row[1], v2 = row[2], v3 = row[3];   // 4x LDS.128 (broadcast)
    u64 a0 = v0.x, a1 = v0.y, a2 = v1.x, a3 = v1.y;
    u64 a4 = v2.x, a5 = v2.y, a6 = v3.x, a7 = v3.y;
    fma2(acc[0],  a0, w0); fma2(acc[1],  a1, w0); fma2(acc[2],  a2, w0); fma2(acc[3],  a3, w0);
    fma2(acc[4],  a4, w0); fma2(acc[5],  a5, w0); fma2(acc[6],  a6, w0); fma2(acc[7],  a7, w0);
    fma2(acc[8],  a0, w1); fma2(acc[9],  a1, w1); fma2(acc[10], a2, w1); fma2(acc[11], a3, w1);
    fma2(acc[12], a4, w1); fma2(acc[13], a5, w1); fma2(acc[14], a6, w1); fma2(acc[15], a7, w1);
    fma2(acc[16], a0, w2); fma2(acc[17], a1, w2); fma2(acc[18], a2, w2); fma2(acc[19], a3, w2);
    fma2(acc[20], a4, w2); fma2(acc[21], a5, w2); fma2(acc[22], a6, w2); fma2(acc[23], a7, w2);
    fma2(acc[24], a0, w3); fma2(acc[25], a1, w3); fma2(acc[26], a2, w3); fma2(acc[27], a3, w3);
    fma2(acc[28], a4, w3); fma2(acc[29], a5, w3); fma2(acc[30], a6, w3); fma2(acc[31], a7, w3);
}

// shared layout (floats)
#define OFF_C   0                                   // 192
#define OFF_E   192                                 // 63*68 = 4284
#define OFF_X   (OFF_E + EDIM * PSTR)               // 4476
#define OFF_Y   (OFF_X + H * PSTR)                  // 21884
#define OFF_OCC (OFF_Y + H * PSTR)                  // 39292 (8 warps x 16 pts)
#define OFF_CLS (OFF_OCC + 128)                     // 39420 (4 parts x 64 pts)
#define SMEM_FLOATS (OFF_CLS + 256)                 // 39676
#define SMEM_BYTES  (SMEM_FLOATS * 4)               // 158704

__global__ void __launch_bounds__(256, 1) mlp3d_kernel(
    const float* __restrict__ coords,
    const float* __restrict__ W0, const float* __restrict__ b0,
    const float* __restrict__ W1, const float* __restrict__ b1,
    const float* __restrict__ W2, const float* __restrict__ b2,
    const float* __restrict__ Wocc, const float* __restrict__ bocc,
    const float* __restrict__ Wc, const float* __restrict__ bc,
    float* __restrict__ out, int N)
{
    extern __shared__ float sm[];
    float* c_s   = sm + OFF_C;
    float* e_s   = sm + OFF_E;
    float* x_s   = sm + OFF_X;
    float* y_s   = sm + OFF_Y;
    float* occ_s = sm + OFF_OCC;
    float* cls_s = sm + OFF_CLS;

    const int t    = threadIdx.x;
    const int lane = t & 31;
    const int warp = t >> 5;
    const int nq   = t & 63;     // neuron quad: neurons j0..j0+3
    const int pg   = t >> 6;     // point group: points m0..m0+15
    const int j0   = nq << 2;
    const int m0   = pg << 4;
    const int n0   = blockIdx.x * TPTS;

    // --- load coords for this tile ---
    if (t < 3 * TPTS) c_s[t] = coords[n0 * 3 + t];
    __syncthreads();

    // --- NeRF positional embedding into e_s[i][m] ---
    for (int idx = t; idx < EDIM * TPTS; idx += 256) {
        int i = idx >> 6, m = idx & 63;
        float v;
        if (i < 3) {
            v = c_s[m * 3 + i];
        } else {
            int k = i - 3;
            int f = k / 6;
            int r = k - 6 * f;                  // 0..5 : [sin x3, cos x3]
            int c = (r >= 3) ? (r - 3) : r;
            float arg = c_s[m * 3 + c] * (float)(1 << f);
            float sv, cv;
            sincosf(arg, &sv, &cv);
            v = (r < 3) ? sv : cv;
        }
        e_s[i * PSTR + m] = v;
    }
    __syncthreads();

    u64 acc[32];

    // =================== layer 0: x = e @ W0 + b0 (no relu) ===================
    {
        float4 bv = *(const float4*)(b0 + j0);
        u64 bb[4] = {pk2(bv.x), pk2(bv.y), pk2(bv.z), pk2(bv.w)};
        #pragma unroll
        for (int jj = 0; jj < 4; jj++)
            #pragma unroll
            for (int kk = 0; kk < 8; kk++) acc[jj * 8 + kk] = bb[jj];
        #pragma unroll 3
        for (int i = 0; i < EDIM; i++) accum_row(acc, W0, e_s, i, j0, m0);
        #pragma unroll
        for (int jj = 0; jj < 4; jj++) {
            u64x2* xr = (u64x2*)(x_s + (j0 + jj) * PSTR + m0);
            #pragma unroll
            for (int q = 0; q < 4; q++) {
                u64x2 v; v.x = acc[jj * 8 + 2 * q]; v.y = acc[jj * 8 + 2 * q + 1];
                xr[q] = v;
            }
        }
    }
    __syncthreads();

    // ====== layer 1 (trunk) MERGED with part branch ======
    // Iterate i starting at this thread's own part block; after 64 rows,
    // acc = b1 + masked-block sum -> emit the class head, then finish the trunk.
    u64 cls[8];
    {
        const int p   = nq >> 4;            // part owning neurons j0..j0+3
        const int i0p = p << 6;
        float4 bv = *(const float4*)(b1 + j0);
        u64 bb[4] = {pk2(bv.x), pk2(bv.y), pk2(bv.z), pk2(bv.w)};
        #pragma unroll
        for (int jj = 0; jj < 4; jj++)
            #pragma unroll
            for (int kk = 0; kk < 8; kk++) acc[jj * 8 + kk] = bb[jj];

        #pragma unroll 4
        for (int ii = 0; ii < 64; ii++) accum_row(acc, W1, x_s, i0p + ii, j0, m0);

        // part head: cls_p[m] = sum_j relu(acc_j) * Wc[p][j]
        float4 wv = *(const float4*)(Wc + p * H + j0);
        u64 w0 = pk2(wv.x), w1 = pk2(wv.y), w2 = pk2(wv.z), w3 = pk2(wv.w);
        #pragma unroll
        for (int kk = 0; kk < 8; kk++) {
            cls[kk] = mul2(relu2(acc[kk]), w0);
            fma2(cls[kk], relu2(acc[8 + kk]),  w1);
            fma2(cls[kk], relu2(acc[16 + kk]), w2);
            fma2(cls[kk], relu2(acc[24 + kk]), w3);
        }
        // each part = 16 quads = one half-warp -> 4-round butterfly
        #pragma unroll
        for (int off = 8; off; off >>= 1)
            #pragma unroll
            for (int kk = 0; kk < 8; kk++)
                cls[kk] = add2(cls[kk], shfl_xor_u64(cls[kk], off));

        // finish the trunk sum (remaining 192 rows, wrapped)
        #pragma unroll 4
        for (int ii = 64; ii < 256; ii++)
            accum_row(acc, W1, x_s, (i0p + ii) & (H - 1), j0, m0);

        #pragma unroll
        for (int jj = 0; jj < 4; jj++) {
            u64x2* yr = (u64x2*)(y_s + (j0 + jj) * PSTR + m0);
            #pragma unroll
            for (int q = 0; q < 4; q++) {
                u64x2 v; v.x = relu2(acc[jj * 8 + 2 * q]); v.y = relu2(acc[jj * 8 + 2 * q + 1]);
                yr[q] = v;
            }
        }
        if ((lane & 15) == 0) {
            u64* c = (u64*)cls_s;           // cls_s[p][64 pts]
            #pragma unroll
            for (int kk = 0; kk < 8; kk++) c[p * 32 + (m0 >> 1) + kk] = cls[kk];
        }
    }
    __syncthreads();

    // ========== layer 2 + occ head: z = relu(y @ W2 + b2); occ = z . Wocc ==========
    {
        float4 bv = *(const float4*)(b2 + j0);
        u64 bb[4] = {pk2(bv.x), pk2(bv.y), pk2(bv.z), pk2(bv.w)};
        #pragma unroll
        for (int jj = 0; jj < 4; jj++)
            #pragma unroll
            for (int kk = 0; kk < 8; kk++) acc[jj * 8 + kk] = bb[jj];
        #pragma unroll 4
        for (int i = 0; i < H; i++) accum_row(acc, W2, y_s, i, j0, m0);

        float4 wv = *(const float4*)(Wocc + j0);
        u64 w0 = pk2(wv.x), w1 = pk2(wv.y), w2 = pk2(wv.z), w3 = pk2(wv.w);
        u64 s[8];
        #pragma unroll
        for (int kk = 0; kk < 8; kk++) {
            s[kk] = mul2(relu2(acc[kk]), w0);
            fma2(s[kk], relu2(acc[8 + kk]),  w1);
            fma2(s[kk], relu2(acc[16 + kk]), w2);
            fma2(s[kk], relu2(acc[24 + kk]), w3);
        }
        // reduce the warp's 32 quads (128 neurons)
        #pragma unroll
        for (int off = 16; off; off >>= 1)
            #pragma unroll
            for (int kk = 0; kk < 8; kk++)
                s[kk] = add2(s[kk], shfl_xor_u64(s[kk], off));
        if (lane == 0) {
            u64* o = (u64*)occ_s;           // occ_s[warp][16 pts]
            #pragma unroll
            for (int kk = 0; kk < 8; kk++) o[warp * 8 + kk] = s[kk];
        }
    }
    __syncthreads();

    // --- final writes ---
    if (t < TPTS) {
        int g = t >> 4, r = t & 15;         // point-group g handled by warps 2g, 2g+1
        float o = bocc[0] + occ_s[(2 * g) * 16 + r] + occ_s[(2 * g + 1) * 16 + r];
        out[n0 + t] = o;                                        // occ: first N floats
    }
    {
        int p = t >> 6, m = t & 63;
        out[N + (n0 + m) * 4 + p] = cls_s[p * 64 + m] + bc[p];  // part_class [N,4]
    }
}

extern "C" void kernel_launch(void* const* d_in, const int* in_sizes, int n_in,
                              void* d_out, int out_size) {
    const float* coords = (const float*)d_in[0];
    const float* W0   = (const float*)d_in[1];
    const float* b0   = (const float*)d_in[2];
    const float* W1   = (const float*)d_in[3];
    const float* b1   = (const float*)d_in[4];
    const float* W2   = (const float*)d_in[5];
    const float* b2   = (const float*)d_in[6];
    const float* Wocc = (const float*)d_in[7];
    const float* bocc = (const float*)d_in[8];
    const float* Wc   = (const float*)d_in[9];
    const float* bc   = (const float*)d_in[10];
    float* out = (float*)d_out;

    int N = in_sizes[0] / 3;        // 131072
    int tiles = N / TPTS;           // 2048

    cudaFuncSetAttribute(mlp3d_kernel,
                         cudaFuncAttributeMaxDynamicSharedMemorySize, SMEM_BYTES);
    mlp3d_kernel<<<tiles, 256, SMEM_BYTES>>>(
        coords, W0, b0, W1, b1, W2, b2, Wocc, bocc, Wc, bc, out, N);
}

// round 6
// speedup vs baseline: 1.3111x; 1.3111x over previous
#include <cuda_runtime.h>

#define TPTS 64          // points per tile
#define H    256
#define EDIM 63
#define PSTR 68          // padded point-stride in shared (floats); 272B = 17*16B

typedef unsigned long long u64;
struct __align__(16) u64x2 { u64 x, y; };

// ---- packed f32x2 helpers (FFMA2 is PTX-only on sm_103a) ----
__device__ __forceinline__ u64 pk2(float w) {
    u64 r; asm("mov.b64 %0, {%1, %1};" : "=l"(r) : "f"(w)); return r;
}
__device__ __forceinline__ void fma2(u64 &a, u64 x, u64 w) {
    asm("fma.rn.f32x2 %0, %1, %2, %0;" : "+l"(a) : "l"(x), "l"(w));
}
__device__ __forceinline__ u64 add2(u64 a, u64 b) {
    u64 r; asm("add.rn.f32x2 %0, %1, %2;" : "=l"(r) : "l"(a), "l"(b)); return r;
}
__device__ __forceinline__ u64 mul2(u64 a, u64 b) {
    u64 r; asm("mul.rn.f32x2 %0, %1, %2;" : "=l"(r) : "l"(a), "l"(b)); return r;
}
__device__ __forceinline__ u64 relu2(u64 a) {
    float lo, hi;
    asm("mov.b64 {%0, %1}, %2;" : "=f"(lo), "=f"(hi) : "l"(a));
    lo = fmaxf(lo, 0.0f); hi = fmaxf(hi, 0.0f);
    u64 r; asm("mov.b64 %0, {%1, %2};" : "=l"(r) : "f"(lo), "f"(hi)); return r;
}
__device__ __forceinline__ u64 shfl_xor_u64(u64 v, int off) {
    unsigned lo = (unsigned)v, hi = (unsigned)(v >> 32);
    lo = __shfl_xor_sync(0xffffffffu, lo, off);
    hi = __shfl_xor_sync(0xffffffffu, hi, off);
    return ((u64)hi << 32) | lo;
}

// One input row i: acc[jj*8+kk] += in[i][m0+2kk..+1] * W[i][j0+jj]
// (4 neurons x 16 points per thread)
__device__ __forceinline__ void accum_row(u64 acc[32], const float* __restrict__ W,
                                          const float* in_s, int i, int j0, int m0)
{
    float4 wv = *(const float4*)(W + i * H + j0);          // LDG.128: 4 neuron weights
    u64 w0 = pk2(wv.x), w1 = pk2(wv.y), w2 = pk2(wv.z), w3 = pk2(wv.w);
    const u64x2* row = (const u64x2*)(in_s + i * PSTR + m0);
    u64x2 v0 = row[0], v1 = row[1], v2 = row[2], v3 = row[3];   // 4x LDS.128 (broadcast)
    u64 a0 = v0.x, a1 = v0.y, a2 = v1.x, a3 = v1.y;
    u64 a4 = v2.x, a5 = v2.y, a6 = v3.x, a7 = v3.y;
    fma2(acc[0],  a0, w0); fma2(acc[1],  a1, w0); fma2(acc[2],  a2, w0); fma2(acc[3],  a3, w0);
    fma2(acc[4],  a4, w0); fma2(acc[5],  a5, w0); fma2(acc[6],  a6, w0); fma2(acc[7],  a7, w0);
    fma2(acc[8],  a0, w1); fma2(acc[9],  a1, w1); fma2(acc[10], a2, w1); fma2(acc[11], a3, w1);
    fma2(acc[12], a4, w1); fma2(acc[13], a5, w1); fma2(acc[14], a6, w1); fma2(acc[15], a7, w1);
    fma2(acc[16], a0, w2); fma2(acc[17], a1, w2); fma2(acc[18], a2, w2); fma2(acc[19], a3, w2);
    fma2(acc[20], a4, w2); fma2(acc[21], a5, w2); fma2(acc[22], a6, w2); fma2(acc[23], a7, w2);
    fma2(acc[24], a0, w3); fma2(acc[25], a1, w3); fma2(acc[26], a2, w3); fma2(acc[27], a3, w3);
    fma2(acc[28], a4, w3); fma2(acc[29], a5, w3); fma2(acc[30], a6, w3); fma2(acc[31], a7, w3);
}

// shared layout (floats). x and y ALIAS the same buffer (xy_s): y is written
// only after all reads of x (guarded by __syncthreads on both sides).
#define OFF_C   0                                   // 192
#define OFF_E   192                                 // 63*68 = 4284
#define OFF_XY  (OFF_E + EDIM * PSTR)               // 4476
#define OFF_OCC (OFF_XY + H * PSTR)                 // 21884 (8 warps x 16 pts)
#define OFF_CLS (OFF_OCC + 128)                     // 22012 (4 parts x 64 pts)
#define SMEM_FLOATS (OFF_CLS + 256)                 // 22268
#define SMEM_BYTES  (SMEM_FLOATS * 4)               // 89072 -> 2 CTAs/SM

__global__ void __launch_bounds__(256, 2) mlp3d_kernel(
    const float* __restrict__ coords,
    const float* __restrict__ W0, const float* __restrict__ b0,
    const float* __restrict__ W1, const float* __restrict__ b1,
    const float* __restrict__ W2, const float* __restrict__ b2,
    const float* __restrict__ Wocc, const float* __restrict__ bocc,
    const float* __restrict__ Wc, const float* __restrict__ bc,
    float* __restrict__ out, int N)
{
    extern __shared__ float sm[];
    float* c_s   = sm + OFF_C;
    float* e_s   = sm + OFF_E;
    float* xy_s  = sm + OFF_XY;
    float* occ_s = sm + OFF_OCC;
    float* cls_s = sm + OFF_CLS;

    const int t    = threadIdx.x;
    const int lane = t & 31;
    const int warp = t >> 5;
    const int nq   = t & 63;     // neuron quad: neurons j0..j0+3
    const int pg   = t >> 6;     // point group: points m0..m0+15
    const int j0   = nq << 2;
    const int m0   = pg << 4;
    const int n0   = blockIdx.x * TPTS;

    // --- load coords for this tile ---
    if (t < 3 * TPTS) c_s[t] = coords[n0 * 3 + t];
    __syncthreads();

    // --- NeRF positional embedding into e_s[i][m] ---
    for (int idx = t; idx < EDIM * TPTS; idx += 256) {
        int i = idx >> 6, m = idx & 63;
        float v;
        if (i < 3) {
            v = c_s[m * 3 + i];
        } else {
            int k = i - 3;
            int f = k / 6;
            int r = k - 6 * f;                  // 0..5 : [sin x3, cos x3]
            int c = (r >= 3) ? (r - 3) : r;
            float arg = c_s[m * 3 + c] * (float)(1 << f);
            float sv, cv;
            sincosf(arg, &sv, &cv);
            v = (r < 3) ? sv : cv;
        }
        e_s[i * PSTR + m] = v;
    }
    __syncthreads();

    u64 acc[32];

    // =================== layer 0: x = e @ W0 + b0 (no relu) ===================
    {
        float4 bv = *(const float4*)(b0 + j0);
        u64 bb[4] = {pk2(bv.x), pk2(bv.y), pk2(bv.z), pk2(bv.w)};
        #pragma unroll
        for (int jj = 0; jj < 4; jj++)
            #pragma unroll
            for (int kk = 0; kk < 8; kk++) acc[jj * 8 + kk] = bb[jj];
        #pragma unroll 3
        for (int i = 0; i < EDIM; i++) accum_row(acc, W0, e_s, i, j0, m0);
    }
    __syncthreads();            // e_s reads done (x overwrites nothing; separate region, but keep order)
    {
        #pragma unroll
        for (int jj = 0; jj < 4; jj++) {
            u64x2* xr = (u64x2*)(xy_s + (j0 + jj) * PSTR + m0);
            #pragma unroll
            for (int q = 0; q < 4; q++) {
                u64x2 v; v.x = acc[jj * 8 + 2 * q]; v.y = acc[jj * 8 + 2 * q + 1];
                xr[q] = v;
            }
        }
    }
    __syncthreads();

    // ====== layer 1 (trunk) MERGED with part branch ======
    // Start the i-loop at this thread's own part block; after 64 rows acc is
    // exactly the masked-block pre-activation -> emit class head, then finish.
    {
        const int p   = nq >> 4;            // part owning neurons j0..j0+3
        const int i0p = p << 6;
        float4 bv = *(const float4*)(b1 + j0);
        u64 bb[4] = {pk2(bv.x), pk2(bv.y), pk2(bv.z), pk2(bv.w)};
        #pragma unroll
        for (int jj = 0; jj < 4; jj++)
            #pragma unroll
            for (int kk = 0; kk < 8; kk++) acc[jj * 8 + kk] = bb[jj];

        #pragma unroll 4
        for (int ii = 0; ii < 64; ii++) accum_row(acc, W1, xy_s, i0p + ii, j0, m0);

        // part head NOW (retire cls registers before the long tail)
        {
            float4 wv = *(const float4*)(Wc + p * H + j0);
            u64 w0 = pk2(wv.x), w1 = pk2(wv.y), w2 = pk2(wv.z), w3 = pk2(wv.w);
            u64 cls[8];
            #pragma unroll
            for (int kk = 0; kk < 8; kk++) {
                cls[kk] = mul2(relu2(acc[kk]), w0);
                fma2(cls[kk], relu2(acc[8 + kk]),  w1);
                fma2(cls[kk], relu2(acc[16 + kk]), w2);
                fma2(cls[kk], relu2(acc[24 + kk]), w3);
            }
            // each part = 16 quads = one half-warp -> 4-round butterfly
            #pragma unroll
            for (int off = 8; off; off >>= 1)
                #pragma unroll
                for (int kk = 0; kk < 8; kk++)
                    cls[kk] = add2(cls[kk], shfl_xor_u64(cls[kk], off));
            if ((lane & 15) == 0) {
                u64* c = (u64*)cls_s;       // cls_s[p][64 pts]
                #pragma unroll
                for (int kk = 0; kk < 8; kk++) c[p * 32 + (m0 >> 1) + kk] = cls[kk];
            }
        }

        // finish the trunk sum (remaining 192 rows, wrapped)
        #pragma unroll 4
        for (int ii = 64; ii < 256; ii++)
            accum_row(acc, W1, xy_s, (i0p + ii) & (H - 1), j0, m0);
    }
    __syncthreads();            // all reads of x complete -> safe to overwrite with y
    {
        #pragma unroll
        for (int jj = 0; jj < 4; jj++) {
            u64x2* yr = (u64x2*)(xy_s + (j0 + jj) * PSTR + m0);
            #pragma unroll
            for (int q = 0; q < 4; q++) {
                u64x2 v; v.x = relu2(acc[jj * 8 + 2 * q]); v.y = relu2(acc[jj * 8 + 2 * q + 1]);
                yr[q] = v;
            }
        }
    }
    __syncthreads();

    // ========== layer 2 + occ head: z = relu(y @ W2 + b2); occ = z . Wocc ==========
    {
        float4 bv = *(const float4*)(b2 + j0);
        u64 bb[4] = {pk2(bv.x), pk2(bv.y), pk2(bv.z), pk2(bv.w)};
        #pragma unroll
        for (int jj = 0; jj < 4; jj++)
            #pragma unroll
            for (int kk = 0; kk < 8; kk++) acc[jj * 8 + kk] = bb[jj];
        #pragma unroll 4
        for (int i = 0; i < H; i++) accum_row(acc, W2, xy_s, i, j0, m0);

        float4 wv = *(const float4*)(Wocc + j0);
        u64 w0 = pk2(wv.x), w1 = pk2(wv.y), w2 = pk2(wv.z), w3 = pk2(wv.w);
        u64 s[8];
        #pragma unroll
        for (int kk = 0; kk < 8; kk++) {
            s[kk] = mul2(relu2(acc[kk]), w0);
            fma2(s[kk], relu2(acc[8 + kk]),  w1);
            fma2(s[kk], relu2(acc[16 + kk]), w2);
            fma2(s[kk], relu2(acc[24 + kk]), w3);
        }
        // reduce the warp's 32 quads (128 neurons)
        #pragma unroll
        for (int off = 16; off; off >>= 1)
            #pragma unroll
            for (int kk = 0; kk < 8; kk++)
                s[kk] = add2(s[kk], shfl_xor_u64(s[kk], off));
        if (lane == 0) {
            u64* o = (u64*)occ_s;           // occ_s[warp][16 pts]
            #pragma unroll
            for (int kk = 0; kk < 8; kk++) o[warp * 8 + kk] = s[kk];
        }
    }
    __syncthreads();

    // --- final writes ---
    if (t < TPTS) {
        int g = t >> 4, r = t & 15;         // point-group g handled by warps 2g, 2g+1
        float o = bocc[0] + occ_s[(2 * g) * 16 + r] + occ_s[(2 * g + 1) * 16 + r];
        out[n0 + t] = o;                                        // occ: first N floats
    }
    {
        int p = t >> 6, m = t & 63;
        out[N + (n0 + m) * 4 + p] = cls_s[p * 64 + m] + bc[p];  // part_class [N,4]
    }
}

extern "C" void kernel_launch(void* const* d_in, const int* in_sizes, int n_in,
                              void* d_out, int out_size) {
    const float* coords = (const float*)d_in[0];
    const float* W0   = (const float*)d_in[1];
    const float* b0   = (const float*)d_in[2];
    const float* W1   = (const float*)d_in[3];
    const float* b1   = (const float*)d_in[4];
    const float* W2   = (const float*)d_in[5];
    const float* b2   = (const float*)d_in[6];
    const float* Wocc = (const float*)d_in[7];
    const float* bocc = (const float*)d_in[8];
    const float* Wc   = (const float*)d_in[9];
    const float* bc   = (const float*)d_in[10];
    float* out = (float*)d_out;

    int N = in_sizes[0] / 3;        // 131072
    int tiles = N / TPTS;           // 2048

    cudaFuncSetAttribute(mlp3d_kernel,
                         cudaFuncAttributeMaxDynamicSharedMemorySize, SMEM_BYTES);
    mlp3d_kernel<<<tiles, 256, SMEM_BYTES>>>(
        coords, W0, b0, W1, b1, W2, b2, Wocc, bocc, Wc, bc, out, N);
}